// round 14
// baseline (speedup 1.0000x reference)
#include <cuda_runtime.h>
#include <cuda_fp16.h>
#include <cstdint>
#include <math.h>

// ---------------------------------------------------------------------------
// Problem constants
#define SEQ    512
#define BATCH  64
#define H2     1024
#define DIN    3072
#define KST    2048
#define M_ROWS (SEQ * BATCH)        // 32768
#define NT2    8                    // energy partial slabs (8 n-tiles of 128)
#define KSPLIT 8
#define NSC    8                    // context s-chunks (64 steps each)

// fp32 tiling for the small u GEMM
#define BM 64
#define BN 64
#define BK 16

// Scratch
__device__ __align__(16) float g_upart[KSPLIT * BATCH * H2];
__device__ __align__(16) float g_u[BATCH * H2];
__device__ __align__(16) float g_epart[NT2 * M_ROWS];   // layout [nt][b][s]
__device__ __align__(16) float g_cpart[NSC * BATCH * H2];
__device__ __align__(16) __half g_encH[M_ROWS * H2];    // 64 MB fp16 enc
__device__ __align__(16) __half g_w1H[H2 * H2];         // 2 MB  fp16 W1enc

// ---------------------------------------------------------------------------
// PTX helpers (base ISA only — compiles for sm_103)
// ---------------------------------------------------------------------------
__device__ __forceinline__ uint32_t smem_u32(const void* p) {
    uint32_t a;
    asm("{ .reg .u64 t; cvta.to.shared.u64 t, %1; cvt.u32.u64 %0, t; }" : "=r"(a) : "l"(p));
    return a;
}
// accurate tanh: 1 - 2/(exp2(2*log2e*x)+1)  (~1e-6 abs error)
__device__ __forceinline__ float tanh_ex(float x) {
    float t; asm("ex2.approx.f32 %0, %1;" : "=f"(t) : "f"(x * 2.8853900817779268f));
    float r; asm("rcp.approx.f32 %0, %1;" : "=f"(r) : "f"(t + 1.0f));
    return fmaf(-2.0f, r, 1.0f);
}

#define CP_ASYNC16(dst, src) \
    asm volatile("cp.async.cg.shared.global [%0], [%1], 16;" :: "r"(dst), "l"(src))
#define CP_COMMIT() asm volatile("cp.async.commit_group;" ::: "memory")
#define CP_WAIT1()  asm volatile("cp.async.wait_group 1;" ::: "memory")
#define CP_WAIT0()  asm volatile("cp.async.wait_group 0;" ::: "memory")

__device__ __forceinline__ void ldsm4(uint32_t* d, uint32_t addr) {
    asm volatile("ldmatrix.sync.aligned.m8n8.x4.shared.b16 {%0,%1,%2,%3}, [%4];"
                 : "=r"(d[0]), "=r"(d[1]), "=r"(d[2]), "=r"(d[3]) : "r"(addr));
}
__device__ __forceinline__ void mma16816h(float* d, const uint32_t* a,
                                          uint32_t b0, uint32_t b1) {
    asm volatile("mma.sync.aligned.m16n8k16.row.col.f32.f16.f16.f32 "
                 "{%0,%1,%2,%3}, {%4,%5,%6,%7}, {%8,%9}, {%0,%1,%2,%3};"
                 : "+f"(d[0]), "+f"(d[1]), "+f"(d[2]), "+f"(d[3])
                 : "r"(a[0]), "r"(a[1]), "r"(a[2]), "r"(a[3]), "r"(b0), "r"(b1));
}

// ---------------------------------------------------------------------------
// Kernel P (fused): uGemm partials (blocks 0..127) + fp32->fp16 conversions.
// Conversion blocks process 4 float4s/thread (MLP=4).
//   enc:  8388608 float4s -> 8192 blocks
//   W1:   262144 float4s  ->  256 blocks
// ---------------------------------------------------------------------------
__global__ void prepK(const float* __restrict__ state,
                      const float* __restrict__ enc,
                      const float* __restrict__ W1) {
    __shared__ float As[BK][BM];
    __shared__ float Bs[BK][BN];
    const int bid = blockIdx.x;
    const int tid = threadIdx.x;

    if (bid >= 128) {
        int cb = bid - 128;
        if (cb < 8192) {
            // enc: 4 float4s per thread, stride-256 within a 1024-float4 block
            int idx0 = cb * 1024 + tid;
            float4 v[4];
#pragma unroll
            for (int q = 0; q < 4; q++)
                v[q] = *(const float4*)(enc + (size_t)(idx0 + q * 256) * 4);
#pragma unroll
            for (int q = 0; q < 4; q++) {
                __half2 h01 = __floats2half2_rn(v[q].x, v[q].y);
                __half2 h23 = __floats2half2_rn(v[q].z, v[q].w);
                *(uint2*)(g_encH + (size_t)(idx0 + q * 256) * 4) =
                    make_uint2(*(uint32_t*)&h01, *(uint32_t*)&h23);
            }
        } else {
            // W1enc: 4 float4s per thread
            int idx0 = (cb - 8192) * 1024 + tid;
#pragma unroll
            for (int q = 0; q < 4; q++) {
                int idx = idx0 + q * 256;
                int n = idx >> 8;
                int k = (idx & 255) * 4;
                float4 v = *(const float4*)(W1 + (size_t)n * DIN + KST + k);
                __half2 hh0 = __floats2half2_rn(v.x, v.y);
                __half2 hh1 = __floats2half2_rn(v.z, v.w);
                *(uint2*)(g_w1H + (size_t)n * H2 + k) =
                    make_uint2(*(uint32_t*)&hh0, *(uint32_t*)&hh1);
            }
        }
        return;
    }

    // ---- uGemm partials: n0 = (bid&15)*64, ks = bid>>4 (0..7)
    const int n0 = (bid & 15) * BN;
    const int ks = bid >> 4;
    const int k0base = ks * (KST / KSPLIT);   // 256-wide K slice

    const int tx = tid & 15;
    const int ty = tid >> 4;
    const int lrow = tid >> 2;
    const int lcol = (tid & 3) * 4;

    float acc[4][4];
#pragma unroll
    for (int i = 0; i < 4; i++)
#pragma unroll
        for (int j = 0; j < 4; j++) acc[i][j] = 0.f;

    for (int k0 = k0base; k0 < k0base + (KST / KSPLIT); k0 += BK) {
        int kd = k0 + lcol;
        int l = kd >> 10, kk = kd & 1023;
        float4 a = *(const float4*)&state[((size_t)(l * 64 + lrow)) * 1024 + kk];
        float4 w = *(const float4*)&W1[(size_t)(n0 + lrow) * DIN + kd];
        As[lcol + 0][lrow] = a.x; As[lcol + 1][lrow] = a.y;
        As[lcol + 2][lrow] = a.z; As[lcol + 3][lrow] = a.w;
        Bs[lcol + 0][lrow] = w.x; Bs[lcol + 1][lrow] = w.y;
        Bs[lcol + 2][lrow] = w.z; Bs[lcol + 3][lrow] = w.w;
        __syncthreads();
#pragma unroll
        for (int kk2 = 0; kk2 < BK; kk2++) {
            float4 av = *(const float4*)&As[kk2][ty * 4];
            float4 bv = *(const float4*)&Bs[kk2][tx * 4];
            acc[0][0] += av.x * bv.x; acc[0][1] += av.x * bv.y; acc[0][2] += av.x * bv.z; acc[0][3] += av.x * bv.w;
            acc[1][0] += av.y * bv.x; acc[1][1] += av.y * bv.y; acc[1][2] += av.y * bv.z; acc[1][3] += av.y * bv.w;
            acc[2][0] += av.z * bv.x; acc[2][1] += av.z * bv.y; acc[2][2] += av.z * bv.z; acc[2][3] += av.z * bv.w;
            acc[3][0] += av.w * bv.x; acc[3][1] += av.w * bv.y; acc[3][2] += av.w * bv.z; acc[3][3] += av.w * bv.w;
        }
        __syncthreads();
    }

    float* dst = &g_upart[ks * (BATCH * H2)];
#pragma unroll
    for (int i = 0; i < 4; i++) {
        int b = ty * 4 + i;
#pragma unroll
        for (int j = 0; j < 4; j++) dst[b * H2 + n0 + tx * 4 + j] = acc[i][j];
    }
}

// ---------------------------------------------------------------------------
// Kernel 2: reduce split-K partials + bias -> g_u
// ---------------------------------------------------------------------------
__global__ void reduceU(const float* __restrict__ b1) {
    int idx = blockIdx.x * blockDim.x + threadIdx.x;
    int h = idx & 1023;
    float s = b1[h];
#pragma unroll
    for (int ks = 0; ks < KSPLIT; ks++) s += g_upart[ks * (BATCH * H2) + idx];
    g_u[idx] = s;
}

// ---------------------------------------------------------------------------
// Kernel 3: energy GEMM, fp16 single pass, single-sync 3-stage pipeline,
//           fused tanh/W2 epilogue with cp.async-prefetched u/W2 slabs.
// CTA 128(M) x 128(N), 8 warps (2m x 4n), warp tile 64x32.
// Stage = A(16K) + B(16K) = 32K; 3 stages = 96K -> 2 CTA/SM.
// At c==15, stages 1+2 are dead -> prefetch u[64][132] + w2[128] there.
// ---------------------------------------------------------------------------
#define ST_A   0
#define ST_B   16384
#define ST_SZ  32768
#define EN_SMEM 98304
#define SU_OFF 32768          // u slab: 64 rows * 528 B (pad-132 floats)
#define W2_OFF (32768 + 33792) // 66560

__global__ void __launch_bounds__(256, 2)
energyTC(const float* __restrict__ W2) {
    extern __shared__ char smem[];
    const uint32_t sb = smem_u32(smem);
    const int tid = threadIdx.x;
    const int wid = tid >> 5;
    const int lane = tid & 31;
    const int wm = wid >> 2;      // 0..1
    const int wn = wid & 3;       // 0..3
    const int m0 = blockIdx.x * 128;
    const int n0 = blockIdx.y * 128;

    float acc[4][4][4];
#pragma unroll
    for (int i = 0; i < 4; i++)
#pragma unroll
        for (int j = 0; j < 4; j++)
#pragma unroll
            for (int k = 0; k < 4; k++) acc[i][j][k] = 0.f;

    // ---- precomputed cp.async addressing
    const int r_ld = tid >> 3;        // base row 0..31
    const int g_ld = tid & 7;         // 16B group 0..7
    const __half* pE[4];
    const __half* pW[4];
    uint32_t sO[4];
#pragma unroll
    for (int t = 0; t < 4; t++) {
        int r = r_ld + t * 32;
        pE[t] = g_encH + (size_t)(m0 + r) * H2 + g_ld * 8;
        pW[t] = g_w1H + (size_t)(n0 + r) * H2 + g_ld * 8;
        sO[t] = (uint32_t)(r * 128 + ((g_ld ^ (r & 7)) << 4));
    }

    // ---- precomputed ldmatrix bases (XOR-folded swizzle)
    const int laneLo = lane & 15;
    const int hiA = lane >> 4;            // 0/1
    const int hiB = (lane >> 3) & 1;      // 0/1
    uint32_t baseA[4], baseB[2];
#pragma unroll
    for (int mi = 0; mi < 4; mi++) {
        int r = wm * 64 + mi * 16 + laneLo;
        baseA[mi] = (uint32_t)(r * 128 + ((((r & 7) ^ hiA)) << 4));
    }
#pragma unroll
    for (int p = 0; p < 2; p++) {
        int n = wn * 32 + p * 16 + (lane & 7) + ((lane >> 4) & 1) * 8;
        baseB[p] = (uint32_t)(n * 128 + ((((n & 7) ^ hiB)) << 4));
    }

#define ISSUE(stg, k0)                                                          \
    do {                                                                        \
        uint32_t _s = sb + (stg) * ST_SZ;                                       \
        _Pragma("unroll")                                                       \
        for (int t = 0; t < 4; t++) {                                           \
            CP_ASYNC16(_s + ST_A + sO[t], pE[t] + (k0));                        \
            CP_ASYNC16(_s + ST_B + sO[t], pW[t] + (k0));                        \
        }                                                                       \
        CP_COMMIT();                                                            \
    } while (0)

    ISSUE(0, 0);
    ISSUE(1, 64);

    for (int c = 0; c < 16; c++) {
        if (c < 15) CP_WAIT1(); else CP_WAIT0();
        __syncthreads();   // chunk-c visible; all warps done reading stage (c-1)%3

        if (c == 15) {
            // Stages 1 and 2 are dead (readers passed the barrier above).
            // Prefetch u[64][132] slab + w2[128] there, overlapped with the
            // final chunk's compute.
#pragma unroll
            for (int q = 0; q < 8; q++) {
                int i = tid + q * 256;      // 0..2047 16B chunks
                int b = i >> 5;             // row 0..63
                int nc = i & 31;            // 16B chunk within 128-float row
                CP_ASYNC16(sb + SU_OFF + b * 528 + nc * 16,
                           g_u + b * H2 + n0 + nc * 4);
            }
            if (tid < 32)
                CP_ASYNC16(sb + W2_OFF + tid * 16, W2 + n0 + tid * 4);
            CP_COMMIT();
        }

        const uint32_t stg = sb + (c % 3) * ST_SZ;
        const uint32_t tA = stg + ST_A, tB = stg + ST_B;

#pragma unroll
        for (int s = 0; s < 2; s++) {
            uint32_t a[4][4], b[2][4];
#pragma unroll
            for (int mi = 0; mi < 4; mi++)
                ldsm4(a[mi], tA + (baseA[mi] ^ (s << 5)));
            ldsm4(b[0], tB + (baseB[0] ^ (s << 5)));
            ldsm4(b[1], tB + (baseB[1] ^ (s << 5)));
#pragma unroll
            for (int mi = 0; mi < 4; mi++)
#pragma unroll
                for (int nj = 0; nj < 4; nj++)
                    mma16816h(acc[mi][nj], a[mi], b[nj >> 1][(nj & 1) * 2],
                              b[nj >> 1][(nj & 1) * 2 + 1]);
        }

        if (c + 2 <= 15) ISSUE((c + 2) % 3, (c + 2) * 64);

#pragma unroll
        for (int s = 2; s < 4; s++) {
            uint32_t a[4][4], b[2][4];
#pragma unroll
            for (int mi = 0; mi < 4; mi++)
                ldsm4(a[mi], tA + (baseA[mi] ^ (s << 5)));
            ldsm4(b[0], tB + (baseB[0] ^ (s << 5)));
            ldsm4(b[1], tB + (baseB[1] ^ (s << 5)));
#pragma unroll
            for (int mi = 0; mi < 4; mi++)
#pragma unroll
                for (int nj = 0; nj < 4; nj++)
                    mma16816h(acc[mi][nj], a[mi], b[nj >> 1][(nj & 1) * 2],
                              b[nj >> 1][(nj & 1) * 2 + 1]);
        }
    }
    CP_WAIT0();        // prefetch group complete
    __syncthreads();   // visible to all warps

    // ---- epilogue: u/w2 already staged; red at smem+0 (stage 0 dead now)
    float* su  = (float*)(smem + SU_OFF);      // [64][132]
    float* sw2 = (float*)(smem + W2_OFF);      // [128]
    float* red = (float*)smem;                 // [128][4]

    {
        const int g = lane >> 2, t = lane & 3;
        float part[4][2];
#pragma unroll
        for (int mi = 0; mi < 4; mi++) { part[mi][0] = 0.f; part[mi][1] = 0.f; }

#pragma unroll
        for (int mi = 0; mi < 4; mi++) {
            int r_lo = wm * 64 + mi * 16 + g;
            int b_lo = r_lo & 63;
            int b_hi = (r_lo + 8) & 63;
#pragma unroll
            for (int nj = 0; nj < 4; nj++) {
                int n = wn * 32 + nj * 8 + 2 * t;
                float w0 = sw2[n], w1 = sw2[n + 1];
                float z00 = acc[mi][nj][0] + su[b_lo * 132 + n];
                float z01 = acc[mi][nj][1] + su[b_lo * 132 + n + 1];
                float z10 = acc[mi][nj][2] + su[b_hi * 132 + n];
                float z11 = acc[mi][nj][3] + su[b_hi * 132 + n + 1];
                part[mi][0] += w0 * tanh_ex(z00) + w1 * tanh_ex(z01);
                part[mi][1] += w0 * tanh_ex(z10) + w1 * tanh_ex(z11);
            }
        }
#pragma unroll
        for (int o = 1; o <= 2; o <<= 1)
#pragma unroll
            for (int mi = 0; mi < 4; mi++) {
                part[mi][0] += __shfl_xor_sync(0xffffffffu, part[mi][0], o);
                part[mi][1] += __shfl_xor_sync(0xffffffffu, part[mi][1], o);
            }
        if (t == 0) {
#pragma unroll
            for (int mi = 0; mi < 4; mi++) {
                red[(wm * 64 + mi * 16 + g) * 4 + wn]     = part[mi][0];
                red[(wm * 64 + mi * 16 + g + 8) * 4 + wn] = part[mi][1];
            }
        }
    }
    __syncthreads();

    if (tid < 128) {
        float s = red[tid * 4 + 0] + red[tid * 4 + 1] + red[tid * 4 + 2] + red[tid * 4 + 3];
        int b = tid & 63;
        int sIdx = blockIdx.x * 2 + (tid >> 6);
        g_epart[(size_t)blockIdx.y * M_ROWS + b * SEQ + sIdx] = s;
    }
}

// ---------------------------------------------------------------------------
// Kernel 4: fused softmax + partial context.
// grid = (2 h-chunks, 64 b, 8 s-chunks), 256 threads.
// ---------------------------------------------------------------------------
__global__ void softCtxP(float* __restrict__ out) {
    const int hc  = blockIdx.x;
    const int b   = blockIdx.y;
    const int sc  = blockIdx.z;
    const int tid = threadIdx.x;

    __shared__ float sa[512];
    __shared__ float red[256];

    float e0 = 0.f, e1 = 0.f;
#pragma unroll
    for (int nt = 0; nt < NT2; nt++) {
        e0 += g_epart[nt * M_ROWS + b * SEQ + tid];
        e1 += g_epart[nt * M_ROWS + b * SEQ + tid + 256];
    }

    red[tid] = fmaxf(e0, e1);
    __syncthreads();
    for (int off = 128; off > 0; off >>= 1) {
        if (tid < off) red[tid] = fmaxf(red[tid], red[tid + off]);
        __syncthreads();
    }
    float mx = red[0];
    __syncthreads();

    float x0 = expf(e0 - mx);
    float x1 = expf(e1 - mx);
    red[tid] = x0 + x1;
    __syncthreads();
    for (int off = 128; off > 0; off >>= 1) {
        if (tid < off) red[tid] += red[tid + off];
        __syncthreads();
    }
    float inv = 1.0f / red[0];

    float a0 = x0 * inv, a1 = x1 * inv;
    sa[tid] = a0;
    sa[tid + 256] = a1;
    if (hc == 0 && sc == 0) {
        out[BATCH * H2 + b * SEQ + tid]       = a0;
        out[BATCH * H2 + b * SEQ + tid + 256] = a1;
    }
    __syncthreads();

    // partial context over s in [sc*64, sc*64+64)
    const int hp = hc * 256 + tid;               // half2 index 0..511
    const int s0 = sc * 64;
    const __half2* base = (const __half2*)g_encH + (size_t)b * 512 + hp
                        + (size_t)s0 * (BATCH * 512);
    float2 c0 = {0.f, 0.f}, c1 = {0.f, 0.f}, c2 = {0.f, 0.f}, c3 = {0.f, 0.f};
#pragma unroll 4
    for (int s = 0; s < 64; s += 4) {
        float2 f0 = __half22float2(base[(size_t)(s + 0) * (BATCH * 512)]);
        float2 f1 = __half22float2(base[(size_t)(s + 1) * (BATCH * 512)]);
        float2 f2 = __half22float2(base[(size_t)(s + 2) * (BATCH * 512)]);
        float2 f3 = __half22float2(base[(size_t)(s + 3) * (BATCH * 512)]);
        c0.x += sa[s0 + s + 0] * f0.x; c0.y += sa[s0 + s + 0] * f0.y;
        c1.x += sa[s0 + s + 1] * f1.x; c1.y += sa[s0 + s + 1] * f1.y;
        c2.x += sa[s0 + s + 2] * f2.x; c2.y += sa[s0 + s + 2] * f2.y;
        c3.x += sa[s0 + s + 3] * f3.x; c3.y += sa[s0 + s + 3] * f3.y;
    }
    float rx = (c0.x + c1.x) + (c2.x + c3.x);
    float ry = (c0.y + c1.y) + (c2.y + c3.y);
    float* dst = &g_cpart[(size_t)sc * (BATCH * H2) + (size_t)b * H2 + hp * 2];
    dst[0] = rx;
    dst[1] = ry;
}

// ---------------------------------------------------------------------------
// Kernel 5: sum the 8 context partials -> out (deterministic fixed order)
// ---------------------------------------------------------------------------
__global__ void ctxReduce(float* __restrict__ out) {
    int idx = blockIdx.x * blockDim.x + threadIdx.x;   // 0..65535
    float s01 = g_cpart[idx]                  + g_cpart[1 * BATCH * H2 + idx];
    float s23 = g_cpart[2 * BATCH * H2 + idx] + g_cpart[3 * BATCH * H2 + idx];
    float s45 = g_cpart[4 * BATCH * H2 + idx] + g_cpart[5 * BATCH * H2 + idx];
    float s67 = g_cpart[6 * BATCH * H2 + idx] + g_cpart[7 * BATCH * H2 + idx];
    out[idx] = (s01 + s23) + (s45 + s67);
}

// ---------------------------------------------------------------------------
extern "C" void kernel_launch(void* const* d_in, const int* in_sizes, int n_in,
                              void* d_out, int out_size) {
    const float* state = (const float*)d_in[0];
    const float* enc   = (const float*)d_in[1];
    const float* W1    = (const float*)d_in[2];
    const float* b1    = (const float*)d_in[3];
    const float* W2    = (const float*)d_in[4];
    float* out = (float*)d_out;

    cudaFuncSetAttribute(energyTC, cudaFuncAttributeMaxDynamicSharedMemorySize, EN_SMEM);

    prepK<<<128 + 8192 + 256, 256>>>(state, enc, W1);
    reduceU<<<256, 256>>>(b1);
    energyTC<<<dim3(M_ROWS / 128, NT2), 256, EN_SMEM>>>(W2);
    softCtxP<<<dim3(2, BATCH, NSC), 256>>>(out);
    ctxReduce<<<256, 256>>>(out);
}

// round 15
// speedup vs baseline: 1.5454x; 1.5454x over previous
#include <cuda_runtime.h>
#include <cuda_fp16.h>
#include <cstdint>
#include <math.h>

// ---------------------------------------------------------------------------
// Problem constants
#define SEQ    512
#define BATCH  64
#define H2     1024
#define DIN    3072
#define KST    2048
#define M_ROWS (SEQ * BATCH)        // 32768
#define NT2    8                    // energy partial slabs (8 n-tiles of 128)
#define KSPLIT 8
#define NSC    8                    // context s-chunks (64 steps each)

// fp32 tiling for the small u GEMM
#define BM 64
#define BN 64
#define BK 16

// Scratch
__device__ __align__(16) float g_upart[KSPLIT * BATCH * H2];
__device__ __align__(16) float g_u[BATCH * H2];
__device__ __align__(16) float g_epart[NT2 * M_ROWS];   // layout [nt][b][s]
__device__ __align__(16) float g_cpart[NSC * BATCH * H2];
__device__ __align__(16) __half g_encH[M_ROWS * H2];    // 64 MB fp16 enc
__device__ __align__(16) __half g_w1H[H2 * H2];         // 2 MB  fp16 W1enc

// ---------------------------------------------------------------------------
// PTX helpers (base ISA only — compiles for sm_103)
// ---------------------------------------------------------------------------
__device__ __forceinline__ uint32_t smem_u32(const void* p) {
    uint32_t a;
    asm("{ .reg .u64 t; cvta.to.shared.u64 t, %1; cvt.u32.u64 %0, t; }" : "=r"(a) : "l"(p));
    return a;
}
// accurate tanh: 1 - 2/(exp2(2*log2e*x)+1)  (~1e-6 abs error)
__device__ __forceinline__ float tanh_ex(float x) {
    float t; asm("ex2.approx.f32 %0, %1;" : "=f"(t) : "f"(x * 2.8853900817779268f));
    float r; asm("rcp.approx.f32 %0, %1;" : "=f"(r) : "f"(t + 1.0f));
    return fmaf(-2.0f, r, 1.0f);
}

#define CP_ASYNC16(dst, src) \
    asm volatile("cp.async.cg.shared.global [%0], [%1], 16;" :: "r"(dst), "l"(src))
#define CP_COMMIT() asm volatile("cp.async.commit_group;" ::: "memory")
#define CP_WAIT1()  asm volatile("cp.async.wait_group 1;" ::: "memory")
#define CP_WAIT0()  asm volatile("cp.async.wait_group 0;" ::: "memory")

__device__ __forceinline__ void ldsm4(uint32_t* d, uint32_t addr) {
    asm volatile("ldmatrix.sync.aligned.m8n8.x4.shared.b16 {%0,%1,%2,%3}, [%4];"
                 : "=r"(d[0]), "=r"(d[1]), "=r"(d[2]), "=r"(d[3]) : "r"(addr));
}
__device__ __forceinline__ void mma16816h(float* d, const uint32_t* a,
                                          uint32_t b0, uint32_t b1) {
    asm volatile("mma.sync.aligned.m16n8k16.row.col.f32.f16.f16.f32 "
                 "{%0,%1,%2,%3}, {%4,%5,%6,%7}, {%8,%9}, {%0,%1,%2,%3};"
                 : "+f"(d[0]), "+f"(d[1]), "+f"(d[2]), "+f"(d[3])
                 : "r"(a[0]), "r"(a[1]), "r"(a[2]), "r"(a[3]), "r"(b0), "r"(b1));
}

// ---------------------------------------------------------------------------
// Kernel P (fused): uGemm partials (blocks 0..127) + fp32->fp16 conversions.
// Conversion blocks process 4 float4s/thread (MLP=4).
//   enc:  8388608 float4s -> 8192 blocks
//   W1:   262144 float4s  ->  256 blocks
// ---------------------------------------------------------------------------
__global__ void prepK(const float* __restrict__ state,
                      const float* __restrict__ enc,
                      const float* __restrict__ W1) {
    __shared__ float As[BK][BM];
    __shared__ float Bs[BK][BN];
    const int bid = blockIdx.x;
    const int tid = threadIdx.x;

    if (bid >= 128) {
        int cb = bid - 128;
        if (cb < 8192) {
            // enc: 4 float4s per thread, stride-256 within a 1024-float4 block
            int idx0 = cb * 1024 + tid;
            float4 v[4];
#pragma unroll
            for (int q = 0; q < 4; q++)
                v[q] = *(const float4*)(enc + (size_t)(idx0 + q * 256) * 4);
#pragma unroll
            for (int q = 0; q < 4; q++) {
                __half2 h01 = __floats2half2_rn(v[q].x, v[q].y);
                __half2 h23 = __floats2half2_rn(v[q].z, v[q].w);
                *(uint2*)(g_encH + (size_t)(idx0 + q * 256) * 4) =
                    make_uint2(*(uint32_t*)&h01, *(uint32_t*)&h23);
            }
        } else {
            // W1enc: 4 float4s per thread
            int idx0 = (cb - 8192) * 1024 + tid;
#pragma unroll
            for (int q = 0; q < 4; q++) {
                int idx = idx0 + q * 256;
                int n = idx >> 8;
                int k = (idx & 255) * 4;
                float4 v = *(const float4*)(W1 + (size_t)n * DIN + KST + k);
                __half2 hh0 = __floats2half2_rn(v.x, v.y);
                __half2 hh1 = __floats2half2_rn(v.z, v.w);
                *(uint2*)(g_w1H + (size_t)n * H2 + k) =
                    make_uint2(*(uint32_t*)&hh0, *(uint32_t*)&hh1);
            }
        }
        return;
    }

    // ---- uGemm partials: n0 = (bid&15)*64, ks = bid>>4 (0..7)
    const int n0 = (bid & 15) * BN;
    const int ks = bid >> 4;
    const int k0base = ks * (KST / KSPLIT);   // 256-wide K slice

    const int tx = tid & 15;
    const int ty = tid >> 4;
    const int lrow = tid >> 2;
    const int lcol = (tid & 3) * 4;

    float acc[4][4];
#pragma unroll
    for (int i = 0; i < 4; i++)
#pragma unroll
        for (int j = 0; j < 4; j++) acc[i][j] = 0.f;

    for (int k0 = k0base; k0 < k0base + (KST / KSPLIT); k0 += BK) {
        int kd = k0 + lcol;
        int l = kd >> 10, kk = kd & 1023;
        float4 a = *(const float4*)&state[((size_t)(l * 64 + lrow)) * 1024 + kk];
        float4 w = *(const float4*)&W1[(size_t)(n0 + lrow) * DIN + kd];
        As[lcol + 0][lrow] = a.x; As[lcol + 1][lrow] = a.y;
        As[lcol + 2][lrow] = a.z; As[lcol + 3][lrow] = a.w;
        Bs[lcol + 0][lrow] = w.x; Bs[lcol + 1][lrow] = w.y;
        Bs[lcol + 2][lrow] = w.z; Bs[lcol + 3][lrow] = w.w;
        __syncthreads();
#pragma unroll
        for (int kk2 = 0; kk2 < BK; kk2++) {
            float4 av = *(const float4*)&As[kk2][ty * 4];
            float4 bv = *(const float4*)&Bs[kk2][tx * 4];
            acc[0][0] += av.x * bv.x; acc[0][1] += av.x * bv.y; acc[0][2] += av.x * bv.z; acc[0][3] += av.x * bv.w;
            acc[1][0] += av.y * bv.x; acc[1][1] += av.y * bv.y; acc[1][2] += av.y * bv.z; acc[1][3] += av.y * bv.w;
            acc[2][0] += av.z * bv.x; acc[2][1] += av.z * bv.y; acc[2][2] += av.z * bv.z; acc[2][3] += av.z * bv.w;
            acc[3][0] += av.w * bv.x; acc[3][1] += av.w * bv.y; acc[3][2] += av.w * bv.z; acc[3][3] += av.w * bv.w;
        }
        __syncthreads();
    }

    float* dst = &g_upart[ks * (BATCH * H2)];
#pragma unroll
    for (int i = 0; i < 4; i++) {
        int b = ty * 4 + i;
#pragma unroll
        for (int j = 0; j < 4; j++) dst[b * H2 + n0 + tx * 4 + j] = acc[i][j];
    }
}

// ---------------------------------------------------------------------------
// Kernel 2: reduce split-K partials + bias -> g_u
// ---------------------------------------------------------------------------
__global__ void reduceU(const float* __restrict__ b1) {
    int idx = blockIdx.x * blockDim.x + threadIdx.x;
    int h = idx & 1023;
    float s = b1[h];
#pragma unroll
    for (int ks = 0; ks < KSPLIT; ks++) s += g_upart[ks * (BATCH * H2) + idx];
    g_u[idx] = s;
}

// ---------------------------------------------------------------------------
// Kernel 3: energy GEMM, fp16 single pass, single-sync 3-stage pipeline,
//           fused tanh/W2 epilogue.  (round-13 configuration — verbatim)
// CTA 128(M) x 128(N), 8 warps (2m x 4n), warp tile 64x32.
// Stage = A(16K) + B(16K) = 32K; 3 stages = 96K -> 2 CTA/SM.
// ---------------------------------------------------------------------------
#define ST_A   0
#define ST_B   16384
#define ST_SZ  32768
#define EN_SMEM 98304

__global__ void __launch_bounds__(256, 2)
energyTC(const float* __restrict__ W2) {
    extern __shared__ char smem[];
    const uint32_t sb = smem_u32(smem);
    const int tid = threadIdx.x;
    const int wid = tid >> 5;
    const int lane = tid & 31;
    const int wm = wid >> 2;      // 0..1
    const int wn = wid & 3;       // 0..3
    const int m0 = blockIdx.x * 128;
    const int n0 = blockIdx.y * 128;

    float acc[4][4][4];
#pragma unroll
    for (int i = 0; i < 4; i++)
#pragma unroll
        for (int j = 0; j < 4; j++)
#pragma unroll
            for (int k = 0; k < 4; k++) acc[i][j][k] = 0.f;

    // ---- precomputed cp.async addressing
    const int r_ld = tid >> 3;        // base row 0..31
    const int g_ld = tid & 7;         // 16B group 0..7
    const __half* pE[4];
    const __half* pW[4];
    uint32_t sO[4];
#pragma unroll
    for (int t = 0; t < 4; t++) {
        int r = r_ld + t * 32;
        pE[t] = g_encH + (size_t)(m0 + r) * H2 + g_ld * 8;
        pW[t] = g_w1H + (size_t)(n0 + r) * H2 + g_ld * 8;
        sO[t] = (uint32_t)(r * 128 + ((g_ld ^ (r & 7)) << 4));
    }

    // ---- precomputed ldmatrix bases (XOR-folded swizzle)
    const int laneLo = lane & 15;
    const int hiA = lane >> 4;            // 0/1
    const int hiB = (lane >> 3) & 1;      // 0/1
    uint32_t baseA[4], baseB[2];
#pragma unroll
    for (int mi = 0; mi < 4; mi++) {
        int r = wm * 64 + mi * 16 + laneLo;
        baseA[mi] = (uint32_t)(r * 128 + ((((r & 7) ^ hiA)) << 4));
    }
#pragma unroll
    for (int p = 0; p < 2; p++) {
        int n = wn * 32 + p * 16 + (lane & 7) + ((lane >> 4) & 1) * 8;
        baseB[p] = (uint32_t)(n * 128 + ((((n & 7) ^ hiB)) << 4));
    }

#define ISSUE(stg, k0)                                                          \
    do {                                                                        \
        uint32_t _s = sb + (stg) * ST_SZ;                                       \
        _Pragma("unroll")                                                       \
        for (int t = 0; t < 4; t++) {                                           \
            CP_ASYNC16(_s + ST_A + sO[t], pE[t] + (k0));                        \
            CP_ASYNC16(_s + ST_B + sO[t], pW[t] + (k0));                        \
        }                                                                       \
        CP_COMMIT();                                                            \
    } while (0)

    ISSUE(0, 0);
    ISSUE(1, 64);

    for (int c = 0; c < 16; c++) {
        if (c < 15) CP_WAIT1(); else CP_WAIT0();
        __syncthreads();   // chunk-c visible; all warps done reading stage (c-1)%3

        const uint32_t stg = sb + (c % 3) * ST_SZ;
        const uint32_t tA = stg + ST_A, tB = stg + ST_B;

#pragma unroll
        for (int s = 0; s < 2; s++) {
            uint32_t a[4][4], b[2][4];
#pragma unroll
            for (int mi = 0; mi < 4; mi++)
                ldsm4(a[mi], tA + (baseA[mi] ^ (s << 5)));
            ldsm4(b[0], tB + (baseB[0] ^ (s << 5)));
            ldsm4(b[1], tB + (baseB[1] ^ (s << 5)));
#pragma unroll
            for (int mi = 0; mi < 4; mi++)
#pragma unroll
                for (int nj = 0; nj < 4; nj++)
                    mma16816h(acc[mi][nj], a[mi], b[nj >> 1][(nj & 1) * 2],
                              b[nj >> 1][(nj & 1) * 2 + 1]);
        }

        if (c + 2 <= 15) ISSUE((c + 2) % 3, (c + 2) * 64);

#pragma unroll
        for (int s = 2; s < 4; s++) {
            uint32_t a[4][4], b[2][4];
#pragma unroll
            for (int mi = 0; mi < 4; mi++)
                ldsm4(a[mi], tA + (baseA[mi] ^ (s << 5)));
            ldsm4(b[0], tB + (baseB[0] ^ (s << 5)));
            ldsm4(b[1], tB + (baseB[1] ^ (s << 5)));
#pragma unroll
            for (int mi = 0; mi < 4; mi++)
#pragma unroll
                for (int nj = 0; nj < 4; nj++)
                    mma16816h(acc[mi][nj], a[mi], b[nj >> 1][(nj & 1) * 2],
                              b[nj >> 1][(nj & 1) * 2 + 1]);
        }
    }
    __syncthreads();

    // ---- epilogue: stage u[64][128] (pad 132) + w2[128] + red[128][4] in smem
    float* su  = (float*)smem;                 // 33792 B
    float* sw2 = (float*)(smem + 33792);       // 512 B
    float* red = (float*)(smem + 34304);       // 2048 B
    for (int i = tid; i < 64 * 128; i += 256) {
        int b = i >> 7, n = i & 127;
        su[b * 132 + n] = g_u[b * H2 + n0 + n];
    }
    if (tid < 128) sw2[tid] = W2[n0 + tid];
    __syncthreads();

    {
        const int g = lane >> 2, t = lane & 3;
        float part[4][2];
#pragma unroll
        for (int mi = 0; mi < 4; mi++) { part[mi][0] = 0.f; part[mi][1] = 0.f; }

#pragma unroll
        for (int mi = 0; mi < 4; mi++) {
            int r_lo = wm * 64 + mi * 16 + g;
            int b_lo = r_lo & 63;
            int b_hi = (r_lo + 8) & 63;
#pragma unroll
            for (int nj = 0; nj < 4; nj++) {
                int n = wn * 32 + nj * 8 + 2 * t;
                float w0 = sw2[n], w1 = sw2[n + 1];
                float z00 = acc[mi][nj][0] + su[b_lo * 132 + n];
                float z01 = acc[mi][nj][1] + su[b_lo * 132 + n + 1];
                float z10 = acc[mi][nj][2] + su[b_hi * 132 + n];
                float z11 = acc[mi][nj][3] + su[b_hi * 132 + n + 1];
                part[mi][0] += w0 * tanh_ex(z00) + w1 * tanh_ex(z01);
                part[mi][1] += w0 * tanh_ex(z10) + w1 * tanh_ex(z11);
            }
        }
#pragma unroll
        for (int o = 1; o <= 2; o <<= 1)
#pragma unroll
            for (int mi = 0; mi < 4; mi++) {
                part[mi][0] += __shfl_xor_sync(0xffffffffu, part[mi][0], o);
                part[mi][1] += __shfl_xor_sync(0xffffffffu, part[mi][1], o);
            }
        if (t == 0) {
#pragma unroll
            for (int mi = 0; mi < 4; mi++) {
                red[(wm * 64 + mi * 16 + g) * 4 + wn]     = part[mi][0];
                red[(wm * 64 + mi * 16 + g + 8) * 4 + wn] = part[mi][1];
            }
        }
    }
    __syncthreads();

    if (tid < 128) {
        float s = red[tid * 4 + 0] + red[tid * 4 + 1] + red[tid * 4 + 2] + red[tid * 4 + 3];
        int b = tid & 63;
        int sIdx = blockIdx.x * 2 + (tid >> 6);
        g_epart[(size_t)blockIdx.y * M_ROWS + b * SEQ + sIdx] = s;
    }
}

// ---------------------------------------------------------------------------
// Kernel 4: fused softmax + partial context.
// grid = (2 h-chunks, 64 b, 8 s-chunks), 256 threads.
// ---------------------------------------------------------------------------
__global__ void softCtxP(float* __restrict__ out) {
    const int hc  = blockIdx.x;
    const int b   = blockIdx.y;
    const int sc  = blockIdx.z;
    const int tid = threadIdx.x;

    __shared__ float sa[512];
    __shared__ float red[256];

    float e0 = 0.f, e1 = 0.f;
#pragma unroll
    for (int nt = 0; nt < NT2; nt++) {
        e0 += g_epart[nt * M_ROWS + b * SEQ + tid];
        e1 += g_epart[nt * M_ROWS + b * SEQ + tid + 256];
    }

    red[tid] = fmaxf(e0, e1);
    __syncthreads();
    for (int off = 128; off > 0; off >>= 1) {
        if (tid < off) red[tid] = fmaxf(red[tid], red[tid + off]);
        __syncthreads();
    }
    float mx = red[0];
    __syncthreads();

    float x0 = expf(e0 - mx);
    float x1 = expf(e1 - mx);
    red[tid] = x0 + x1;
    __syncthreads();
    for (int off = 128; off > 0; off >>= 1) {
        if (tid < off) red[tid] += red[tid + off];
        __syncthreads();
    }
    float inv = 1.0f / red[0];

    float a0 = x0 * inv, a1 = x1 * inv;
    sa[tid] = a0;
    sa[tid + 256] = a1;
    if (hc == 0 && sc == 0) {
        out[BATCH * H2 + b * SEQ + tid]       = a0;
        out[BATCH * H2 + b * SEQ + tid + 256] = a1;
    }
    __syncthreads();

    // partial context over s in [sc*64, sc*64+64)
    const int hp = hc * 256 + tid;               // half2 index 0..511
    const int s0 = sc * 64;
    const __half2* base = (const __half2*)g_encH + (size_t)b * 512 + hp
                        + (size_t)s0 * (BATCH * 512);
    float2 c0 = {0.f, 0.f}, c1 = {0.f, 0.f}, c2 = {0.f, 0.f}, c3 = {0.f, 0.f};
#pragma unroll 4
    for (int s = 0; s < 64; s += 4) {
        float2 f0 = __half22float2(base[(size_t)(s + 0) * (BATCH * 512)]);
        float2 f1 = __half22float2(base[(size_t)(s + 1) * (BATCH * 512)]);
        float2 f2 = __half22float2(base[(size_t)(s + 2) * (BATCH * 512)]);
        float2 f3 = __half22float2(base[(size_t)(s + 3) * (BATCH * 512)]);
        c0.x += sa[s0 + s + 0] * f0.x; c0.y += sa[s0 + s + 0] * f0.y;
        c1.x += sa[s0 + s + 1] * f1.x; c1.y += sa[s0 + s + 1] * f1.y;
        c2.x += sa[s0 + s + 2] * f2.x; c2.y += sa[s0 + s + 2] * f2.y;
        c3.x += sa[s0 + s + 3] * f3.x; c3.y += sa[s0 + s + 3] * f3.y;
    }
    float rx = (c0.x + c1.x) + (c2.x + c3.x);
    float ry = (c0.y + c1.y) + (c2.y + c3.y);
    float* dst = &g_cpart[(size_t)sc * (BATCH * H2) + (size_t)b * H2 + hp * 2];
    dst[0] = rx;
    dst[1] = ry;
}

// ---------------------------------------------------------------------------
// Kernel 5: sum the 8 context partials -> out (deterministic fixed order)
// ---------------------------------------------------------------------------
__global__ void ctxReduce(float* __restrict__ out) {
    int idx = blockIdx.x * blockDim.x + threadIdx.x;   // 0..65535
    float s01 = g_cpart[idx]                  + g_cpart[1 * BATCH * H2 + idx];
    float s23 = g_cpart[2 * BATCH * H2 + idx] + g_cpart[3 * BATCH * H2 + idx];
    float s45 = g_cpart[4 * BATCH * H2 + idx] + g_cpart[5 * BATCH * H2 + idx];
    float s67 = g_cpart[6 * BATCH * H2 + idx] + g_cpart[7 * BATCH * H2 + idx];
    out[idx] = (s01 + s23) + (s45 + s67);
}

// ---------------------------------------------------------------------------
extern "C" void kernel_launch(void* const* d_in, const int* in_sizes, int n_in,
                              void* d_out, int out_size) {
    const float* state = (const float*)d_in[0];
    const float* enc   = (const float*)d_in[1];
    const float* W1    = (const float*)d_in[2];
    const float* b1    = (const float*)d_in[3];
    const float* W2    = (const float*)d_in[4];
    float* out = (float*)d_out;

    cudaFuncSetAttribute(energyTC, cudaFuncAttributeMaxDynamicSharedMemorySize, EN_SMEM);

    prepK<<<128 + 8192 + 256, 256>>>(state, enc, W1);
    reduceU<<<256, 256>>>(b1);
    energyTC<<<dim3(M_ROWS / 128, NT2), 256, EN_SMEM>>>(W2);
    softCtxP<<<dim3(2, BATCH, NSC), 256>>>(out);
    ctxReduce<<<256, 256>>>(out);
}